// round 3
// baseline (speedup 1.0000x reference)
#include <cuda_runtime.h>

// SSKernelNPLR: S4 NPLR kernel generation, H=256, N=64, c=1, rank=1, L=2048.
// One block per head h. Phases:
//  1) stage v[a,b,n] = Bcat[a]*Ccat[b] and w_dt into smem
//  2) Cauchy sums over n for each FFT node f (F=1025), Woodbury combine,
//     write Hermitian-extended spectrum X[0..2047] into smem
//  3) 2048-pt inverse complex FFT (radix-2 Stockham, smem ping-pong),
//     write Re(.)/L to gmem.

#define NSTATE 64
#define LFULL  2048
#define FHALF  1025

__device__ __forceinline__ float2 cmul(float2 a, float2 b) {
    return make_float2(a.x * b.x - a.y * b.y, a.x * b.y + a.y * b.x);
}

__global__ __launch_bounds__(256)
void ssk_nplr_kernel(const float* __restrict__ Cin,
                     const float* __restrict__ Bin,
                     const float* __restrict__ Pin,
                     const float* __restrict__ Win,
                     const float* __restrict__ log_dt,
                     float* __restrict__ out)
{
    __shared__ float2 X[LFULL];      // spectrum / FFT ping  (16 KB)
    __shared__ float2 Y[LFULL];      // FFT pong             (16 KB)
    __shared__ float2 T[LFULL / 2];  // twiddles exp(+2*pi*i*k/L) (8 KB)
    __shared__ float2 swd[NSTATE];   // w * dt
    __shared__ float2 sv[4][NSTATE]; // v00, v01, v10, v11

    const int h   = blockIdx.x;
    const int tid = threadIdx.x;
    const float dt = expf(log_dt[h]);

    // ---- Phase 1: stage per-head data ----
    if (tid < NSTATE) {
        const int base = (h * NSTATE + tid) * 2;
        float2 b = make_float2(Bin[base], Bin[base + 1]);
        float2 c = make_float2(Cin[base], Cin[base + 1]);
        float2 p = make_float2(Pin[base], Pin[base + 1]);
        float2 q = make_float2(p.x, -p.y);          // Q = conj(P)
        swd[tid]  = make_float2(Win[base] * dt, Win[base + 1] * dt);
        sv[0][tid] = cmul(b, c);   // B*C
        sv[1][tid] = cmul(b, q);   // B*Q
        sv[2][tid] = cmul(p, c);   // P*C
        sv[3][tid] = cmul(p, q);   // P*Q
    }
    // twiddle table: T[i] = exp(+2*pi*i*i_idx/L)  (inverse transform sign)
    for (int i = tid; i < LFULL / 2; i += 256) {
        float s, c;
        sincospif((float)i * (1.0f / (LFULL / 2)), &s, &c);
        T[i] = make_float2(c, s);
    }
    __syncthreads();

    // ---- Phase 2: Cauchy + Woodbury -> spectrum ----
    for (int f = tid; f < FHALF; f += 256) {
        float2 kf;
        if (f == LFULL / 2) {
            // analytic limit at omega = -1:  k_f -> 0.5 * dt * sum_n v00
            float sx = 0.f, sy = 0.f;
            #pragma unroll 8
            for (int n = 0; n < NSTATE; n++) { sx += sv[0][n].x; sy += sv[0][n].y; }
            kf = make_float2(0.5f * dt * sx, 0.5f * dt * sy);
        } else {
            float s, c;
            sincospif((float)f * (1.0f / (LFULL / 2)), &s, &c);
            float2 om = make_float2(c, -s);                 // exp(-2*pi*i*f/L)
            float2 e  = make_float2(1.0f + om.x, om.y);     // 1 + omega
            float inv_e2 = __fdividef(1.0f, e.x * e.x + e.y * e.y);
            // z = 2*(1-omega)/e  = 2*(1-om)*conj(e)*inv_e2
            float ax = 1.0f - om.x, ay = -om.y;
            float2 z = make_float2(2.0f * (ax * e.x + ay * e.y) * inv_e2,
                                   2.0f * (ay * e.x - ax * e.y) * inv_e2);
            // fac = 2/(1+omega)
            float2 fac = make_float2(2.0f * e.x * inv_e2, -2.0f * e.y * inv_e2);

            float s00x = 0.f, s00y = 0.f, s01x = 0.f, s01y = 0.f;
            float s10x = 0.f, s10y = 0.f, s11x = 0.f, s11y = 0.f;
            #pragma unroll 4
            for (int n = 0; n < NSTATE; n++) {
                float2 wd = swd[n];
                float dx = z.x - wd.x, dy = z.y - wd.y;
                float idd = __fdividef(1.0f, dx * dx + dy * dy);
                float gr = dx * idd, gi = -dy * idd;
                float2 v;
                v = sv[0][n]; s00x += v.x * gr - v.y * gi; s00y += v.x * gi + v.y * gr;
                v = sv[1][n]; s01x += v.x * gr - v.y * gi; s01y += v.x * gi + v.y * gr;
                v = sv[2][n]; s10x += v.x * gr - v.y * gi; s10y += v.x * gi + v.y * gr;
                v = sv[3][n]; s11x += v.x * gr - v.y * gi; s11y += v.x * gi + v.y * gr;
            }
            // r_ab = dt * s_ab
            float2 r00 = make_float2(dt * s00x, dt * s00y);
            float2 r01 = make_float2(dt * s01x, dt * s01y);
            float2 r10 = make_float2(dt * s10x, dt * s10y);
            float2 r11 = make_float2(dt * s11x, dt * s11y);
            // num = r00 - r01*r10/(1+r11)
            float2 t  = cmul(r01, r10);
            float2 d  = make_float2(1.0f + r11.x, r11.y);
            float iD  = __fdividef(1.0f, d.x * d.x + d.y * d.y);
            float2 t2 = make_float2((t.x * d.x + t.y * d.y) * iD,
                                    (t.y * d.x - t.x * d.y) * iD);
            float2 num = make_float2(r00.x - t2.x, r00.y - t2.y);
            kf = cmul(num, fac);
        }
        X[f] = kf;
        if (f > 0 && f < LFULL / 2)
            X[LFULL - f] = make_float2(kf.x, -kf.y);  // Hermitian extension
    }
    __syncthreads();

    // ---- Phase 3: 2048-pt inverse complex FFT (Stockham, autosorted) ----
    float2* src = X;
    float2* dst = Y;
    for (int m = 1; m <= LFULL / 2; m <<= 1) {
        for (int b = tid; b < LFULL / 2; b += 256) {
            int jm = b & ~(m - 1);          // (b / m) * m
            float2 c0 = src[b];
            float2 c1 = src[b + LFULL / 2];
            float2 w  = T[jm];
            dst[b + jm]     = make_float2(c0.x + c1.x, c0.y + c1.y);
            float2 df = make_float2(c0.x - c1.x, c0.y - c1.y);
            dst[b + jm + m] = cmul(w, df);
        }
        __syncthreads();
        float2* tmp = src; src = dst; dst = tmp;
    }

    // ---- Output: real part, scaled by 1/L ----
    const float scale = 1.0f / (float)LFULL;
    float* o = out + (size_t)h * LFULL;
    for (int i = tid; i < LFULL; i += 256)
        o[i] = src[i].x * scale;
}

extern "C" void kernel_launch(void* const* d_in, const int* in_sizes, int n_in,
                              void* d_out, int out_size)
{
    (void)in_sizes; (void)n_in; (void)out_size;
    const float* C  = (const float*)d_in[0];
    const float* B  = (const float*)d_in[1];
    const float* P  = (const float*)d_in[2];
    const float* W  = (const float*)d_in[3];
    const float* ld = (const float*)d_in[4];
    float* out = (float*)d_out;
    ssk_nplr_kernel<<<256, 256>>>(C, B, P, W, ld, out);
}

// round 5
// speedup vs baseline: 1.0570x; 1.0570x over previous
#include <cuda_runtime.h>

// SSKernelNPLR: H=256, N=64, c=1, rank=1, L=2048. One block per head.
// R3: Cauchy phase reworked — 4 freq nodes per thread (amortize LDS 4x),
//     packed f32x2 FFMA2 accumulation via inline PTX.

#define NSTATE 64
#define LFULL  2048

typedef unsigned long long u64;

__device__ __forceinline__ u64 pk2(float lo, float hi) {
    u64 r; asm("mov.b64 %0,{%1,%2};" : "=l"(r) : "f"(lo), "f"(hi)); return r;
}
__device__ __forceinline__ void up2(u64 v, float& lo, float& hi) {
    asm("mov.b64 {%0,%1},%2;" : "=f"(lo), "=f"(hi) : "l"(v));
}
__device__ __forceinline__ u64 add2(u64 a, u64 b) {
    u64 r; asm("add.rn.f32x2 %0,%1,%2;" : "=l"(r) : "l"(a), "l"(b)); return r;
}
__device__ __forceinline__ u64 mul2(u64 a, u64 b) {
    u64 r; asm("mul.rn.f32x2 %0,%1,%2;" : "=l"(r) : "l"(a), "l"(b)); return r;
}
__device__ __forceinline__ u64 ffma2(u64 a, u64 b, u64 c) {
    u64 r; asm("fma.rn.f32x2 %0,%1,%2,%3;" : "=l"(r) : "l"(a), "l"(b), "l"(c)); return r;
}
__device__ __forceinline__ float frcp(float x) {
    float r; asm("rcp.approx.f32 %0,%1;" : "=f"(r) : "f"(x)); return r;
}
__device__ __forceinline__ float2 cmul(float2 a, float2 b) {
    return make_float2(a.x * b.x - a.y * b.y, a.x * b.y + a.y * b.x);
}

__global__ __launch_bounds__(256)
void ssk_nplr_kernel(const float* __restrict__ Cin,
                     const float* __restrict__ Bin,
                     const float* __restrict__ Pin,
                     const float* __restrict__ Win,
                     const float* __restrict__ log_dt,
                     float* __restrict__ out)
{
    __shared__ float2 X[LFULL];        // spectrum / FFT ping (16 KB)
    __shared__ float2 Y[LFULL];        // FFT pong            (16 KB)
    __shared__ float2 T[LFULL / 2];    // twiddles            (8 KB)
    __shared__ u64 swn[NSTATE];        // packed (-w*dt.re, -w*dt.im)
    __shared__ u64 svxx[4][NSTATE];    // packed (v.x, v.x) for v00,v01,v10,v11
    __shared__ u64 svyy[4][NSTATE];    // packed (v.y, v.y)

    const int h   = blockIdx.x;
    const int tid = threadIdx.x;
    const float dt = expf(log_dt[h]);

    // ---- Phase 1: stage per-head data (packed) ----
    if (tid < NSTATE) {
        const int base = (h * NSTATE + tid) * 2;
        float2 b = make_float2(Bin[base], Bin[base + 1]);
        float2 c = make_float2(Cin[base], Cin[base + 1]);
        float2 p = make_float2(Pin[base], Pin[base + 1]);
        float2 q = make_float2(p.x, -p.y);          // Q = conj(P)
        swn[tid] = pk2(-Win[base] * dt, -Win[base + 1] * dt);
        float2 v;
        v = cmul(b, c); svxx[0][tid] = pk2(v.x, v.x); svyy[0][tid] = pk2(v.y, v.y);
        v = cmul(b, q); svxx[1][tid] = pk2(v.x, v.x); svyy[1][tid] = pk2(v.y, v.y);
        v = cmul(p, c); svxx[2][tid] = pk2(v.x, v.x); svyy[2][tid] = pk2(v.y, v.y);
        v = cmul(p, q); svxx[3][tid] = pk2(v.x, v.x); svyy[3][tid] = pk2(v.y, v.y);
    }
    for (int i = tid; i < LFULL / 2; i += 256) {
        float s, c;
        sincospif((float)i * (1.0f / (LFULL / 2)), &s, &c);
        T[i] = make_float2(c, s);                   // exp(+2*pi*i*k/L)
    }
    __syncthreads();

    // ---- Phase 2: Cauchy + Woodbury, 4 nodes per thread ----
    u64 zp[4];
    float2 facv[4];
    #pragma unroll
    for (int k = 0; k < 4; k++) {
        const int f = tid + k * 256;                // 0..1023
        float s, c;
        sincospif((float)f * (1.0f / (LFULL / 2)), &s, &c);
        float2 om = make_float2(c, -s);             // exp(-2*pi*i*f/L)
        float ex = 1.0f + om.x, ey = om.y;          // 1 + omega
        float inv_e2 = frcp(ex * ex + ey * ey);
        float ax = 1.0f - om.x, ay = -om.y;         // 1 - omega
        zp[k] = pk2(2.0f * (ax * ex + ay * ey) * inv_e2,
                    2.0f * (ay * ex - ax * ey) * inv_e2);
        facv[k] = make_float2(2.0f * ex * inv_e2, -2.0f * ey * inv_e2);
    }

    u64 acc[4][4];
    #pragma unroll
    for (int k = 0; k < 4; k++)
        #pragma unroll
        for (int a = 0; a < 4; a++) acc[k][a] = 0ull;

    #pragma unroll 2
    for (int n = 0; n < NSTATE; n++) {
        const u64 wn = swn[n];
        const u64 x0 = svxx[0][n], x1 = svxx[1][n], x2 = svxx[2][n], x3 = svxx[3][n];
        const u64 y0 = svyy[0][n], y1 = svyy[1][n], y2 = svyy[2][n], y3 = svyy[3][n];
        #pragma unroll
        for (int k = 0; k < 4; k++) {
            u64 d = add2(zp[k], wn);                // z - w*dt (wn pre-negated)
            float dx, dy; up2(d, dx, dy);
            float idd = frcp(dx * dx + dy * dy);
            u64 g  = mul2(d, pk2(idd, -idd));       // (gr, gi) = (dx,-dy)*idd
            u64 gs = mul2(pk2(dy, dx), pk2(idd, idd)); // (-gi, gr)
            acc[k][0] = ffma2(x0, g, acc[k][0]); acc[k][0] = ffma2(y0, gs, acc[k][0]);
            acc[k][1] = ffma2(x1, g, acc[k][1]); acc[k][1] = ffma2(y1, gs, acc[k][1]);
            acc[k][2] = ffma2(x2, g, acc[k][2]); acc[k][2] = ffma2(y2, gs, acc[k][2]);
            acc[k][3] = ffma2(x3, g, acc[k][3]); acc[k][3] = ffma2(y3, gs, acc[k][3]);
        }
    }

    #pragma unroll
    for (int k = 0; k < 4; k++) {
        const int f = tid + k * 256;
        float2 r00, r01, r10, r11;
        up2(acc[k][0], r00.x, r00.y); up2(acc[k][1], r01.x, r01.y);
        up2(acc[k][2], r10.x, r10.y); up2(acc[k][3], r11.x, r11.y);
        r00.x *= dt; r00.y *= dt;  r01.x *= dt; r01.y *= dt;
        r10.x *= dt; r10.y *= dt;  r11.x *= dt; r11.y *= dt;
        // num = r00 - r01*r10/(1+r11)
        float2 t = cmul(r01, r10);
        float2 d = make_float2(1.0f + r11.x, r11.y);
        float iD = frcp(d.x * d.x + d.y * d.y);
        float2 t2 = make_float2((t.x * d.x + t.y * d.y) * iD,
                                (t.y * d.x - t.x * d.y) * iD);
        float2 kf = cmul(make_float2(r00.x - t2.x, r00.y - t2.y), facv[k]);
        X[f] = kf;
        if (f > 0)
            X[LFULL - f] = make_float2(kf.x, -kf.y);   // Hermitian mirror
    }
    // f = 1024: analytic limit at omega = -1: k_f -> 0.5*dt*sum_n v00
    if (tid == 0) {
        float sx = 0.f, sy = 0.f;
        #pragma unroll 8
        for (int n = 0; n < NSTATE; n++) {
            float vx, vy, du;
            up2(svxx[0][n], vx, du); up2(svyy[0][n], vy, du);
            sx += vx; sy += vy;
        }
        X[LFULL / 2] = make_float2(0.5f * dt * sx, 0.5f * dt * sy);
    }
    __syncthreads();

    // ---- Phase 3: 2048-pt inverse complex FFT (Stockham) ----
    float2* src = X;
    float2* dst = Y;
    for (int m = 1; m <= LFULL / 2; m <<= 1) {
        for (int b = tid; b < LFULL / 2; b += 256) {
            int jm = b & ~(m - 1);
            float2 c0 = src[b];
            float2 c1 = src[b + LFULL / 2];
            float2 w  = T[jm];
            dst[b + jm]     = make_float2(c0.x + c1.x, c0.y + c1.y);
            float2 df = make_float2(c0.x - c1.x, c0.y - c1.y);
            dst[b + jm + m] = cmul(w, df);
        }
        __syncthreads();
        float2* tmp = src; src = dst; dst = tmp;
    }

    // ---- Output: real part / L ----
    const float scale = 1.0f / (float)LFULL;
    float* o = out + (size_t)h * LFULL;
    for (int i = tid; i < LFULL; i += 256)
        o[i] = src[i].x * scale;
}

extern "C" void kernel_launch(void* const* d_in, const int* in_sizes, int n_in,
                              void* d_out, int out_size)
{
    (void)in_sizes; (void)n_in; (void)out_size;
    const float* C  = (const float*)d_in[0];
    const float* B  = (const float*)d_in[1];
    const float* P  = (const float*)d_in[2];
    const float* W  = (const float*)d_in[3];
    const float* ld = (const float*)d_in[4];
    float* out = (float*)d_out;
    ssk_nplr_kernel<<<256, 256>>>(C, B, P, W, ld, out);
}

// round 6
// speedup vs baseline: 1.1544x; 1.0922x over previous
#include <cuda_runtime.h>

// SSKernelNPLR: H=256, N=64, c=1, rank=1, L=2048.
// R5: split into two kernels for load balance.
//  K1: Cauchy + Woodbury -> spectrum scratch. 1024 blocks (256 heads x 4 chunks),
//      128 threads, 2 freq nodes/thread. f32x2 FFMA2 with only 2 ALU packs/iter,
//      v11 real (one FFMA2 saved).
//  K2: Hermitian mirror + 2048-pt inverse Stockham FFT per head -> out.

#define NSTATE 64
#define LFULL  2048

typedef unsigned long long u64;

__device__ float2 g_spec[256 * 1025];   // 2.05 MB scratch spectrum

__device__ __forceinline__ u64 pk2(float lo, float hi) {
    u64 r; asm("mov.b64 %0,{%1,%2};" : "=l"(r) : "f"(lo), "f"(hi)); return r;
}
__device__ __forceinline__ void up2(u64 v, float& lo, float& hi) {
    asm("mov.b64 {%0,%1},%2;" : "=f"(lo), "=f"(hi) : "l"(v));
}
__device__ __forceinline__ u64 ffma2(u64 a, u64 b, u64 c) {
    u64 r; asm("fma.rn.f32x2 %0,%1,%2,%3;" : "=l"(r) : "l"(a), "l"(b), "l"(c)); return r;
}
__device__ __forceinline__ float frcp(float x) {
    float r; asm("rcp.approx.f32 %0,%1;" : "=f"(r) : "f"(x)); return r;
}
__device__ __forceinline__ float2 cmul(float2 a, float2 b) {
    return make_float2(a.x * b.x - a.y * b.y, a.x * b.y + a.y * b.x);
}

// ---------------- K1: Cauchy + Woodbury ----------------
__global__ __launch_bounds__(128)
void cauchy_kernel(const float* __restrict__ Cin,
                   const float* __restrict__ Bin,
                   const float* __restrict__ Pin,
                   const float* __restrict__ Win,
                   const float* __restrict__ log_dt)
{
    __shared__ float2 swd[NSTATE];     // (-w*dt)
    __shared__ u64 svA[4][NSTATE];     // pk(vx, -vx)   (a = v00,v01,v10,v11)
    __shared__ u64 svB[3][NSTATE];     // pk(vy,  vy)   (v11 imag == 0)

    const int bid   = blockIdx.x;
    const int h     = bid >> 2;
    const int chunk = bid & 3;
    const int tid   = threadIdx.x;
    const float dt  = expf(log_dt[h]);

    if (tid < NSTATE) {
        const int base = (h * NSTATE + tid) * 2;
        float2 b = make_float2(Bin[base], Bin[base + 1]);
        float2 c = make_float2(Cin[base], Cin[base + 1]);
        float2 p = make_float2(Pin[base], Pin[base + 1]);
        float2 q = make_float2(p.x, -p.y);          // Q = conj(P)
        swd[tid] = make_float2(-Win[base] * dt, -Win[base + 1] * dt);
        float2 v;
        v = cmul(b, c); svA[0][tid] = pk2(v.x, -v.x); svB[0][tid] = pk2(v.y, v.y);
        v = cmul(b, q); svA[1][tid] = pk2(v.x, -v.x); svB[1][tid] = pk2(v.y, v.y);
        v = cmul(p, c); svA[2][tid] = pk2(v.x, -v.x); svB[2][tid] = pk2(v.y, v.y);
        float v11 = p.x * p.x + p.y * p.y;          // P*conj(P) is real
        svA[3][tid] = pk2(v11, -v11);
    }
    __syncthreads();

    // two frequency nodes per thread: f = chunk*256 + k*128 + tid
    float zx[2], zy[2];
    float2 facv[2];
    #pragma unroll
    for (int k = 0; k < 2; k++) {
        const int f = chunk * 256 + k * 128 + tid;  // 0..1023
        float s, c;
        sincospif((float)f * (1.0f / (LFULL / 2)), &s, &c);
        float2 om = make_float2(c, -s);             // exp(-2*pi*i*f/L)
        float ex = 1.0f + om.x, ey = om.y;          // 1 + omega
        float inv_e2 = frcp(ex * ex + ey * ey);
        float ax = 1.0f - om.x, ay = -om.y;         // 1 - omega
        zx[k] = 2.0f * (ax * ex + ay * ey) * inv_e2;
        zy[k] = 2.0f * (ay * ex - ax * ey) * inv_e2;
        facv[k] = make_float2(2.0f * ex * inv_e2, -2.0f * ey * inv_e2);
    }

    u64 acc[2][4];
    #pragma unroll
    for (int k = 0; k < 2; k++)
        #pragma unroll
        for (int a = 0; a < 4; a++) acc[k][a] = 0ull;

    #pragma unroll 4
    for (int n = 0; n < NSTATE; n++) {
        const float2 wd = swd[n];
        const u64 a0 = svA[0][n], a1 = svA[1][n], a2 = svA[2][n], a3 = svA[3][n];
        const u64 b0 = svB[0][n], b1 = svB[1][n], b2 = svB[2][n];
        #pragma unroll
        for (int k = 0; k < 2; k++) {
            float dx = zx[k] + wd.x;                // z - w*dt (wd pre-negated)
            float dy = zy[k] + wd.y;
            float r  = frcp(dx * dx + dy * dy);
            float ur = dx * r, ui = dy * r;         // 1/d = (ur, -ui)
            u64 P1 = pk2(ur, ui);
            u64 P2 = pk2(ui, ur);
            acc[k][0] = ffma2(a0, P1, acc[k][0]); acc[k][0] = ffma2(b0, P2, acc[k][0]);
            acc[k][1] = ffma2(a1, P1, acc[k][1]); acc[k][1] = ffma2(b1, P2, acc[k][1]);
            acc[k][2] = ffma2(a2, P1, acc[k][2]); acc[k][2] = ffma2(b2, P2, acc[k][2]);
            acc[k][3] = ffma2(a3, P1, acc[k][3]);   // v11 real: no imag term
        }
    }

    #pragma unroll
    for (int k = 0; k < 2; k++) {
        const int f = chunk * 256 + k * 128 + tid;
        float2 r00, r01, r10, r11;
        up2(acc[k][0], r00.x, r00.y); up2(acc[k][1], r01.x, r01.y);
        up2(acc[k][2], r10.x, r10.y); up2(acc[k][3], r11.x, r11.y);
        r00.x *= dt; r00.y *= dt;  r01.x *= dt; r01.y *= dt;
        r10.x *= dt; r10.y *= dt;  r11.x *= dt; r11.y *= dt;
        // num = r00 - r01*r10/(1+r11)
        float2 t = cmul(r01, r10);
        float2 d = make_float2(1.0f + r11.x, r11.y);
        float iD = frcp(d.x * d.x + d.y * d.y);
        float2 t2 = make_float2((t.x * d.x + t.y * d.y) * iD,
                                (t.y * d.x - t.x * d.y) * iD);
        float2 kf = cmul(make_float2(r00.x - t2.x, r00.y - t2.y), facv[k]);
        g_spec[h * 1025 + f] = kf;
    }

    // f = 1024 (omega = -1 analytic limit): k_f = 0.5*dt*sum_n v00
    if (chunk == 0 && tid == 0) {
        float sx = 0.f, sy = 0.f;
        #pragma unroll 8
        for (int n = 0; n < NSTATE; n++) {
            float vx, vxn, vy, du;
            up2(svA[0][n], vx, vxn);
            up2(svB[0][n], vy, du);
            sx += vx; sy += vy;
        }
        g_spec[h * 1025 + 1024] = make_float2(0.5f * dt * sx, 0.5f * dt * sy);
    }
}

// ---------------- K2: inverse FFT ----------------
__global__ __launch_bounds__(256)
void ifft_kernel(float* __restrict__ out)
{
    __shared__ float2 X[LFULL];      // ping (16 KB)
    __shared__ float2 Y[LFULL];      // pong (16 KB)
    __shared__ float2 T[LFULL / 2];  // twiddles (8 KB)

    const int h   = blockIdx.x;
    const int tid = threadIdx.x;

    for (int i = tid; i < LFULL / 2; i += 256) {
        float s, c;
        sincospif((float)i * (1.0f / (LFULL / 2)), &s, &c);
        T[i] = make_float2(c, s);                   // exp(+2*pi*i*k/L)
    }
    const float2* spec = g_spec + h * 1025;
    for (int f = tid; f <= 1024; f += 256) {
        float2 v = spec[f];
        X[f] = v;
        if (f > 0 && f < 1024)
            X[LFULL - f] = make_float2(v.x, -v.y);  // Hermitian mirror
    }
    __syncthreads();

    float2* src = X;
    float2* dst = Y;
    for (int m = 1; m <= LFULL / 2; m <<= 1) {
        for (int b = tid; b < LFULL / 2; b += 256) {
            int jm = b & ~(m - 1);
            float2 c0 = src[b];
            float2 c1 = src[b + LFULL / 2];
            float2 w  = T[jm];
            dst[b + jm]     = make_float2(c0.x + c1.x, c0.y + c1.y);
            float2 df = make_float2(c0.x - c1.x, c0.y - c1.y);
            dst[b + jm + m] = cmul(w, df);
        }
        __syncthreads();
        float2* tmp = src; src = dst; dst = tmp;
    }

    const float scale = 1.0f / (float)LFULL;
    float* o = out + (size_t)h * LFULL;
    for (int i = tid; i < LFULL; i += 256)
        o[i] = src[i].x * scale;
}

extern "C" void kernel_launch(void* const* d_in, const int* in_sizes, int n_in,
                              void* d_out, int out_size)
{
    (void)in_sizes; (void)n_in; (void)out_size;
    const float* C  = (const float*)d_in[0];
    const float* B  = (const float*)d_in[1];
    const float* P  = (const float*)d_in[2];
    const float* W  = (const float*)d_in[3];
    const float* ld = (const float*)d_in[4];
    float* out = (float*)d_out;
    cauchy_kernel<<<1024, 128>>>(C, B, P, W, ld);
    ifft_kernel<<<256, 256>>>(out);
}